// round 11
// baseline (speedup 1.0000x reference)
#include <cuda_runtime.h>
#include <cstdint>

#define DDIM   4096
#define M_ROWS 8192
#define N_ROWS 4096
#define KINT   (DDIM / 4)          // 1024 ints per row

__device__ __align__(256) int8_t g_qx[(size_t)M_ROWS * DDIM];
__device__ __align__(256) int8_t g_qw[(size_t)N_ROWS * DDIM];
__device__ float g_sa[M_ROWS];
__device__ float g_sw[N_ROWS];

__device__ __forceinline__ uint32_t smem_u32(const void* p) {
    uint32_t a;
    asm("{ .reg .u64 t; cvta.to.shared.u64 t, %1; cvt.u32.u64 %0, t; }" : "=r"(a) : "l"(p));
    return a;
}
__device__ __forceinline__ void cp16(uint32_t dst, const void* src) {
    asm volatile("cp.async.cg.shared.global [%0], [%1], 16;" :: "r"(dst), "l"(src) : "memory");
}
#define CP_COMMIT()  asm volatile("cp.async.commit_group;" ::: "memory")
#define CP_WAIT(n)   asm volatile("cp.async.wait_group %0;" :: "n"(n) : "memory")

__device__ __forceinline__ void ldsm4(uint32_t& r0, uint32_t& r1, uint32_t& r2, uint32_t& r3,
                                      uint32_t addr) {
    asm volatile("ldmatrix.sync.aligned.m8n8.x4.shared.b16 {%0,%1,%2,%3}, [%4];"
                 : "=r"(r0), "=r"(r1), "=r"(r2), "=r"(r3) : "r"(addr));
}
__device__ __forceinline__ void imma16832(int* c, const uint32_t* a, const uint32_t* b) {
    asm volatile(
        "mma.sync.aligned.m16n8k32.row.col.s32.s8.s8.s32 "
        "{%0,%1,%2,%3}, {%4,%5,%6,%7}, {%8,%9}, {%0,%1,%2,%3};\n"
        : "+r"(c[0]), "+r"(c[1]), "+r"(c[2]), "+r"(c[3])
        : "r"(a[0]), "r"(a[1]), "r"(a[2]), "r"(a[3]), "r"(b[0]), "r"(b[1]));
}

// ---------------- fused row-wise absmax int8 quantization ----------------
__global__ __launch_bounds__(256) void quant_fused_kernel(
    const float* __restrict__ x, const float* __restrict__ w,
    const float* __restrict__ scales)
{
    const int b    = blockIdx.x;
    const bool isx = (b < M_ROWS);
    const int row  = isx ? b : (b - M_ROWS);
    const int tid  = threadIdx.x;
    const float4* src4 = reinterpret_cast<const float4*>((isx ? x : w) + (size_t)row * DDIM);
    const float4* scl4 = reinterpret_cast<const float4*>(scales);

    float v[16];
    float m = 0.f;
    #pragma unroll
    for (int i = 0; i < 4; i++) {
        int g = i * 256 + tid;
        float4 xv = src4[g];
        float4 s  = scl4[g];
        float t0, t1, t2, t3;
        if (isx) { t0 = xv.x * s.x; t1 = xv.y * s.y; t2 = xv.z * s.z; t3 = xv.w * s.w; }
        else     { t0 = xv.x / s.x; t1 = xv.y / s.y; t2 = xv.z / s.z; t3 = xv.w / s.w; }
        v[i*4+0] = t0; v[i*4+1] = t1; v[i*4+2] = t2; v[i*4+3] = t3;
        m = fmaxf(m, fmaxf(fmaxf(fabsf(t0), fabsf(t1)), fmaxf(fabsf(t2), fabsf(t3))));
    }

    __shared__ float red[8];
    #pragma unroll
    for (int o = 16; o > 0; o >>= 1)
        m = fmaxf(m, __shfl_xor_sync(0xffffffffu, m, o));
    if ((tid & 31) == 0) red[tid >> 5] = m;
    __syncthreads();
    if (tid < 32) {
        float t = (tid < 8) ? red[tid] : 0.f;
        #pragma unroll
        for (int o = 4; o > 0; o >>= 1)
            t = fmaxf(t, __shfl_xor_sync(0xffffffffu, t, o));
        if (tid == 0) red[0] = fmaxf(t, 1e-8f);
    }
    __syncthreads();
    const float absmax = red[0];
    const float qs = 127.f / absmax;

    int* qrow = reinterpret_cast<int*>((isx ? g_qx : g_qw) + (size_t)row * DDIM);
    #pragma unroll
    for (int i = 0; i < 4; i++) {
        int g = i * 256 + tid;
        int packed = 0;
        #pragma unroll
        for (int j = 0; j < 4; j++) {
            float t = rintf(v[i*4+j] * qs);
            t = fminf(fmaxf(t, -127.f), 127.f);
            packed |= ((int)t & 0xff) << (8 * j);
        }
        qrow[g] = packed;
    }
    if (tid == 0) {
        if (isx) g_sa[row] = absmax * (1.f / 127.f);
        else     g_sw[row] = absmax * (1.f / 127.f);
    }
}

// ---------------- mixed-warp hybrid GEMM ----------------
// CTA 128x128, 8 warps. EVERY warp issues both IMMA and dp4a:
//   IMMA: warp w owns m[16w,16w+16) x n[80,128)  (6 IMMAs per k32, issued first)
//   dp4a: thread owns m{ty+16i} x n{tx+16j, j<5} (n[0:80))
// Split 62.5:37.5 matches measured pipe rates (dp4a 512 : IMMA ~293 MAC/cyc/SM).
// K-major swizzled tiles (u ^= r&7, 16B units), 16B cp.async, 3-stage ring.
#define BKI     32                    // K ints per chunk (128 bytes)
#define NCHUNK  (KINT / BKI)          // 32
#define A_BYTES (128 * 128)
#define STAGEB  (2 * A_BYTES)
#define SMEM_BYTES (3 * STAGEB)       // 98304

__global__ __launch_bounds__(256, 2) void gemm_mixed_kernel(
    const float* __restrict__ bias, const float* __restrict__ scales,
    float* __restrict__ out)
{
    extern __shared__ int smem[];
    const uint32_t sb = smem_u32(smem);
    const int tid  = threadIdx.x;
    const int wid  = tid >> 5;
    const int lane = tid & 31;
    const int m0   = blockIdx.y * 128;
    const int n0   = blockIdx.x * 128;

    const int* qxi = reinterpret_cast<const int*>(g_qx);
    const int* qwi = reinterpret_cast<const int*>(g_qw);

    auto load_stage = [&](int c) {
        const uint32_t sbase = sb + (uint32_t)(c % 3) * STAGEB;
        #pragma unroll
        for (int j = 0; j < 4; j++) {
            int idx = j * 256 + tid;          // 0..1023
            int r = idx >> 3, u = idx & 7;
            uint32_t d = (uint32_t)(r * 128 + ((u ^ (r & 7)) << 4));
            cp16(sbase + d,           qxi + (size_t)(m0 + r) * KINT + c * BKI + u * 4);
            cp16(sbase + A_BYTES + d, qwi + (size_t)(n0 + r) * KINT + c * BKI + u * 4);
        }
    };

    // ---- IMMA addressing: A rows [16w,16w+16), B rows (n) [80,128) ----
    uint32_t baseA; int rqA;
    {
        int r = wid * 16 + (lane & 7) + ((lane >> 3) & 1) * 8;
        baseA = (uint32_t)(r * 128);
        rqA   = r & 7;
    }
    const int chA = lane >> 4;
    uint32_t baseB[3]; int rqB[3];
    const int chB = (lane >> 3) & 1;
    #pragma unroll
    for (int p = 0; p < 3; p++) {
        int r = 80 + 16 * p + ((lane >> 4) & 1) * 8 + (lane & 7);
        baseB[p] = (uint32_t)(A_BYTES + r * 128);
        rqB[p]   = r & 7;
    }

    // ---- dp4a addressing: int4 units, swizzle key const per thread ----
    const int ty = tid >> 4;     // 0..15: m rows ty+16i
    const int tx = tid & 15;     // 0..15: n cols tx+16j (j<5)
    const int aSw = ty & 7;
    const int bSw = tx & 7;
    int aIdx[8], bIdx[5];
    #pragma unroll
    for (int i = 0; i < 8; i++) aIdx[i] = (ty + 16 * i) * 8;
    #pragma unroll
    for (int j = 0; j < 5; j++) bIdx[j] = (A_BYTES / 16) + (tx + 16 * j) * 8;

    int accD[8][5];                    // dp4a accumulators
    #pragma unroll
    for (int i = 0; i < 8; i++)
        #pragma unroll
        for (int j = 0; j < 5; j++) accD[i][j] = 0;
    int accI[6][4];                    // IMMA accumulators
    #pragma unroll
    for (int i = 0; i < 6; i++)
        #pragma unroll
        for (int k = 0; k < 4; k++) accI[i][k] = 0;

    load_stage(0); CP_COMMIT();
    load_stage(1); CP_COMMIT();
    for (int c = 0; c < NCHUNK; c++) {
        CP_WAIT(1);
        __syncthreads();
        if (c + 2 < NCHUNK) load_stage(c + 2);
        CP_COMMIT();
        const uint32_t sB = sb + (uint32_t)(c % 3) * STAGEB;
        const int4* tile = reinterpret_cast<const int4*>(smem + (c % 3) * (STAGEB / 4));

        // ---------- IMMA phase: 16 ldsm + 24 IMMA, tensor pipe drains in background ----------
        #pragma unroll
        for (int ks = 0; ks < 4; ks++) {
            uint32_t a[4], b[6][2];
            ldsm4(a[0], a[1], a[2], a[3],
                  sB + baseA + (((2 * ks + chA) ^ rqA) << 4));
            #pragma unroll
            for (int p = 0; p < 3; p++)
                ldsm4(b[2*p][0], b[2*p][1], b[2*p+1][0], b[2*p+1][1],
                      sB + baseB[p] + (((2 * ks + chB) ^ rqB[p]) << 4));
            #pragma unroll
            for (int nt = 0; nt < 6; nt++)
                imma16832(accI[nt], a, b[nt]);
        }

        // ---------- dp4a phase ----------
        #pragma unroll
        for (int u = 0; u < 8; u++) {
            int4 b4[5];
            #pragma unroll
            for (int j = 0; j < 5; j++) b4[j] = tile[bIdx[j] + (u ^ bSw)];
            #pragma unroll
            for (int h = 0; h < 2; h++) {
                int4 a4[4];
                #pragma unroll
                for (int i = 0; i < 4; i++) a4[i] = tile[aIdx[h * 4 + i] + (u ^ aSw)];
                #pragma unroll
                for (int i = 0; i < 4; i++) {
                    int ii = h * 4 + i;
                    #pragma unroll
                    for (int j = 0; j < 5; j++) {
                        accD[ii][j] = __dp4a(a4[i].x, b4[j].x, accD[ii][j]);
                        accD[ii][j] = __dp4a(a4[i].y, b4[j].y, accD[ii][j]);
                        accD[ii][j] = __dp4a(a4[i].z, b4[j].z, accD[ii][j]);
                        accD[ii][j] = __dp4a(a4[i].w, b4[j].w, accD[ii][j]);
                    }
                }
            }
        }
    }

    // ---------- dp4a epilogue: m = m0+ty+16i, n = n0+tx+16j ----------
    {
        float fw[5], fb[5];
        #pragma unroll
        for (int j = 0; j < 5; j++) {
            int n = n0 + tx + 16 * j;
            fw[j] = g_sw[n];
            fb[j] = __ldg(&bias[n]) / __ldg(&scales[n]);
        }
        #pragma unroll
        for (int i = 0; i < 8; i++) {
            int m = m0 + ty + 16 * i;
            float fa = g_sa[m];
            float* orow = out + (size_t)m * N_ROWS + n0 + tx;
            #pragma unroll
            for (int j = 0; j < 5; j++)
                orow[16 * j] = accD[i][j] * fa * fw[j] + fb[j];
        }
    }

    // ---------- IMMA epilogue: rows 16w+(g,g+8), cols 80+nt*8+2tig ----------
    {
        const int g   = lane >> 2;
        const int tig = lane & 3;
        #pragma unroll
        for (int nt = 0; nt < 6; nt++) {
            int n = n0 + 80 + nt * 8 + 2 * tig;
            float fw0 = g_sw[n], fw1 = g_sw[n + 1];
            float fb0 = __ldg(&bias[n])     / __ldg(&scales[n]);
            float fb1 = __ldg(&bias[n + 1]) / __ldg(&scales[n + 1]);
            int mA = m0 + wid * 16 + g;
            float saA = g_sa[mA];
            float saB = g_sa[mA + 8];
            float2 o0, o1;
            o0.x = accI[nt][0] * saA * fw0 + fb0;
            o0.y = accI[nt][1] * saA * fw1 + fb1;
            o1.x = accI[nt][2] * saB * fw0 + fb0;
            o1.y = accI[nt][3] * saB * fw1 + fb1;
            *reinterpret_cast<float2*>(out + (size_t)mA       * N_ROWS + n) = o0;
            *reinterpret_cast<float2*>(out + (size_t)(mA + 8) * N_ROWS + n) = o1;
        }
    }
}

// ---------------- launch ----------------
extern "C" void kernel_launch(void* const* d_in, const int* in_sizes, int n_in,
                              void* d_out, int out_size)
{
    const float* x      = (const float*)d_in[0];
    const float* weight = (const float*)d_in[1];
    const float* bias   = (const float*)d_in[2];
    const float* scales = (const float*)d_in[3];
    float* out = (float*)d_out;

    cudaFuncSetAttribute(gemm_mixed_kernel,
                         cudaFuncAttributeMaxDynamicSharedMemorySize, SMEM_BYTES);

    quant_fused_kernel<<<M_ROWS + N_ROWS, 256>>>(x, weight, scales);

    dim3 grid(N_ROWS / 128, M_ROWS / 128);   // (32, 64)
    gemm_mixed_kernel<<<grid, 256, SMEM_BYTES>>>(bias, scales, out);
}

// round 12
// speedup vs baseline: 1.1117x; 1.1117x over previous
#include <cuda_runtime.h>
#include <cstdint>

#define DDIM   4096
#define M_ROWS 8192
#define N_ROWS 4096
#define KINT   (DDIM / 4)          // 1024 ints per row

__device__ __align__(256) int8_t g_qx[(size_t)M_ROWS * DDIM];
__device__ __align__(256) int8_t g_qw[(size_t)N_ROWS * DDIM];
__device__ float g_sa[M_ROWS];
__device__ float g_sw[N_ROWS];

__device__ __forceinline__ uint32_t smem_u32(const void* p) {
    uint32_t a;
    asm("{ .reg .u64 t; cvta.to.shared.u64 t, %1; cvt.u32.u64 %0, t; }" : "=r"(a) : "l"(p));
    return a;
}
__device__ __forceinline__ void cp16(uint32_t dst, const void* src) {
    asm volatile("cp.async.cg.shared.global [%0], [%1], 16;" :: "r"(dst), "l"(src) : "memory");
}
#define CP_COMMIT()  asm volatile("cp.async.commit_group;" ::: "memory")
#define CP_WAIT(n)   asm volatile("cp.async.wait_group %0;" :: "n"(n) : "memory")

__device__ __forceinline__ void ldsm4(uint32_t& r0, uint32_t& r1, uint32_t& r2, uint32_t& r3,
                                      uint32_t addr) {
    asm volatile("ldmatrix.sync.aligned.m8n8.x4.shared.b16 {%0,%1,%2,%3}, [%4];"
                 : "=r"(r0), "=r"(r1), "=r"(r2), "=r"(r3) : "r"(addr));
}
__device__ __forceinline__ void imma16832(int* c, const uint32_t* a, const uint32_t* b) {
    asm volatile(
        "mma.sync.aligned.m16n8k32.row.col.s32.s8.s8.s32 "
        "{%0,%1,%2,%3}, {%4,%5,%6,%7}, {%8,%9}, {%0,%1,%2,%3};\n"
        : "+r"(c[0]), "+r"(c[1]), "+r"(c[2]), "+r"(c[3])
        : "r"(a[0]), "r"(a[1]), "r"(a[2]), "r"(a[3]), "r"(b[0]), "r"(b[1]));
}

// ---------------- fused row-wise absmax int8 quantization ----------------
__global__ __launch_bounds__(256) void quant_fused_kernel(
    const float* __restrict__ x, const float* __restrict__ w,
    const float* __restrict__ scales)
{
    const int b    = blockIdx.x;
    const bool isx = (b < M_ROWS);
    const int row  = isx ? b : (b - M_ROWS);
    const int tid  = threadIdx.x;
    const float4* src4 = reinterpret_cast<const float4*>((isx ? x : w) + (size_t)row * DDIM);
    const float4* scl4 = reinterpret_cast<const float4*>(scales);

    float v[16];
    float m = 0.f;
    #pragma unroll
    for (int i = 0; i < 4; i++) {
        int g = i * 256 + tid;
        float4 xv = src4[g];
        float4 s  = scl4[g];
        float t0, t1, t2, t3;
        if (isx) { t0 = xv.x * s.x; t1 = xv.y * s.y; t2 = xv.z * s.z; t3 = xv.w * s.w; }
        else     { t0 = xv.x / s.x; t1 = xv.y / s.y; t2 = xv.z / s.z; t3 = xv.w / s.w; }
        v[i*4+0] = t0; v[i*4+1] = t1; v[i*4+2] = t2; v[i*4+3] = t3;
        m = fmaxf(m, fmaxf(fmaxf(fabsf(t0), fabsf(t1)), fmaxf(fabsf(t2), fabsf(t3))));
    }

    __shared__ float red[8];
    #pragma unroll
    for (int o = 16; o > 0; o >>= 1)
        m = fmaxf(m, __shfl_xor_sync(0xffffffffu, m, o));
    if ((tid & 31) == 0) red[tid >> 5] = m;
    __syncthreads();
    if (tid < 32) {
        float t = (tid < 8) ? red[tid] : 0.f;
        #pragma unroll
        for (int o = 4; o > 0; o >>= 1)
            t = fmaxf(t, __shfl_xor_sync(0xffffffffu, t, o));
        if (tid == 0) red[0] = fmaxf(t, 1e-8f);
    }
    __syncthreads();
    const float absmax = red[0];
    const float qs = 127.f / absmax;

    int* qrow = reinterpret_cast<int*>((isx ? g_qx : g_qw) + (size_t)row * DDIM);
    #pragma unroll
    for (int i = 0; i < 4; i++) {
        int g = i * 256 + tid;
        int packed = 0;
        #pragma unroll
        for (int j = 0; j < 4; j++) {
            float t = rintf(v[i*4+j] * qs);
            t = fminf(fmaxf(t, -127.f), 127.f);
            packed |= ((int)t & 0xff) << (8 * j);
        }
        qrow[g] = packed;
    }
    if (tid == 0) {
        if (isx) g_sa[row] = absmax * (1.f / 127.f);
        else     g_sw[row] = absmax * (1.f / 127.f);
    }
}

// ---------------- mixed-warp hybrid GEMM, tensor-paced interleave ----------------
// CTA 128x128, 8 warps, every warp issues both pipes, split 80 dp4a : 48 IMMA.
// Per k32-step: 3 IMMAs -> 160 dp4a -> 3 IMMAs -> 160 dp4a, so aggregate IMMA
// arrival (~0.067/cyc/SM) matches the measured tensor drain (1 per ~13.8 cyc),
// avoiding dispatch-queue backpressure that serialized phases in R11.
#define BKI     32                    // K ints per chunk (128 bytes)
#define NCHUNK  (KINT / BKI)          // 32
#define A_BYTES (128 * 128)
#define STAGEB  (2 * A_BYTES)
#define SMEM_BYTES (3 * STAGEB)       // 98304

__global__ __launch_bounds__(256, 2) void gemm_mixed_kernel(
    const float* __restrict__ bias, const float* __restrict__ scales,
    float* __restrict__ out)
{
    extern __shared__ int smem[];
    const uint32_t sb = smem_u32(smem);
    const int tid  = threadIdx.x;
    const int wid  = tid >> 5;
    const int lane = tid & 31;
    const int m0   = blockIdx.y * 128;
    const int n0   = blockIdx.x * 128;

    const int* qxi = reinterpret_cast<const int*>(g_qx);
    const int* qwi = reinterpret_cast<const int*>(g_qw);

    auto load_stage = [&](int c) {
        const uint32_t sbase = sb + (uint32_t)(c % 3) * STAGEB;
        #pragma unroll
        for (int j = 0; j < 4; j++) {
            int idx = j * 256 + tid;          // 0..1023
            int r = idx >> 3, u = idx & 7;
            uint32_t d = (uint32_t)(r * 128 + ((u ^ (r & 7)) << 4));
            cp16(sbase + d,           qxi + (size_t)(m0 + r) * KINT + c * BKI + u * 4);
            cp16(sbase + A_BYTES + d, qwi + (size_t)(n0 + r) * KINT + c * BKI + u * 4);
        }
    };

    // ---- IMMA addressing: A rows [16w,16w+16), B rows (n) [80,128) ----
    uint32_t baseA; int rqA;
    {
        int r = wid * 16 + (lane & 7) + ((lane >> 3) & 1) * 8;
        baseA = (uint32_t)(r * 128);
        rqA   = r & 7;
    }
    const int chA = lane >> 4;
    uint32_t baseB[3]; int rqB[3];
    const int chB = (lane >> 3) & 1;
    #pragma unroll
    for (int p = 0; p < 3; p++) {
        int r = 80 + 16 * p + ((lane >> 4) & 1) * 8 + (lane & 7);
        baseB[p] = (uint32_t)(A_BYTES + r * 128);
        rqB[p]   = r & 7;
    }

    // ---- dp4a addressing (immediate-offset form: base + 128*i/j + swizzled u) ----
    const int ty = tid >> 4;     // 0..15: m rows ty+16i
    const int tx = tid & 15;     // 0..15: n cols tx+16j (j<5)
    const int aSw = ty & 7;
    const int bSw = tx & 7;
    const int aBaseU = ty * 8;                      // int4 units
    const int bBaseU = (A_BYTES / 16) + tx * 8;

    int accD[8][5];
    #pragma unroll
    for (int i = 0; i < 8; i++)
        #pragma unroll
        for (int j = 0; j < 5; j++) accD[i][j] = 0;
    int accI[6][4];
    #pragma unroll
    for (int i = 0; i < 6; i++)
        #pragma unroll
        for (int k = 0; k < 4; k++) accI[i][k] = 0;

    load_stage(0); CP_COMMIT();
    load_stage(1); CP_COMMIT();
    for (int c = 0; c < NCHUNK; c++) {
        CP_WAIT(1);
        __syncthreads();
        if (c + 2 < NCHUNK) load_stage(c + 2);
        CP_COMMIT();
        const uint32_t sB = sb + (uint32_t)(c % 3) * STAGEB;
        const int4* tile = reinterpret_cast<const int4*>(smem + (c % 3) * (STAGEB / 4));

        #pragma unroll
        for (int ks = 0; ks < 4; ks++) {
            // fragments for this k32 step
            uint32_t a[4], b[6][2];
            ldsm4(a[0], a[1], a[2], a[3],
                  sB + baseA + (((2 * ks + chA) ^ rqA) << 4));
            #pragma unroll
            for (int p = 0; p < 3; p++)
                ldsm4(b[2*p][0], b[2*p][1], b[2*p+1][0], b[2*p+1][1],
                      sB + baseB[p] + (((2 * ks + chB) ^ rqB[p]) << 4));

            #pragma unroll
            for (int half = 0; half < 2; half++) {
                // 3 IMMAs (paced)
                #pragma unroll
                for (int nt = 0; nt < 3; nt++)
                    imma16832(accI[half * 3 + nt], a, b[half * 3 + nt]);

                // one dp4a u-block: u = 2*ks + half
                const int u = 2 * ks + half;
                int4 b4[5];
                #pragma unroll
                for (int j = 0; j < 5; j++)
                    b4[j] = tile[bBaseU + 128 * j + (u ^ bSw)];
                #pragma unroll
                for (int h = 0; h < 2; h++) {
                    int4 a4[4];
                    #pragma unroll
                    for (int i = 0; i < 4; i++)
                        a4[i] = tile[aBaseU + 128 * (h * 4 + i) + (u ^ aSw)];
                    #pragma unroll
                    for (int i = 0; i < 4; i++) {
                        int ii = h * 4 + i;
                        #pragma unroll
                        for (int j = 0; j < 5; j++) {
                            accD[ii][j] = __dp4a(a4[i].x, b4[j].x, accD[ii][j]);
                            accD[ii][j] = __dp4a(a4[i].y, b4[j].y, accD[ii][j]);
                            accD[ii][j] = __dp4a(a4[i].z, b4[j].z, accD[ii][j]);
                            accD[ii][j] = __dp4a(a4[i].w, b4[j].w, accD[ii][j]);
                        }
                    }
                }
            }
        }
    }

    // ---------- dp4a epilogue: m = m0+ty+16i, n = n0+tx+16j ----------
    {
        float fw[5], fb[5];
        #pragma unroll
        for (int j = 0; j < 5; j++) {
            int n = n0 + tx + 16 * j;
            fw[j] = g_sw[n];
            fb[j] = __ldg(&bias[n]) / __ldg(&scales[n]);
        }
        #pragma unroll
        for (int i = 0; i < 8; i++) {
            int m = m0 + ty + 16 * i;
            float fa = g_sa[m];
            float* orow = out + (size_t)m * N_ROWS + n0 + tx;
            #pragma unroll
            for (int j = 0; j < 5; j++)
                orow[16 * j] = accD[i][j] * fa * fw[j] + fb[j];
        }
    }

    // ---------- IMMA epilogue: rows 16w+(g,g+8), cols 80+nt*8+2tig ----------
    {
        const int g   = lane >> 2;
        const int tig = lane & 3;
        #pragma unroll
        for (int nt = 0; nt < 6; nt++) {
            int n = n0 + 80 + nt * 8 + 2 * tig;
            float fw0 = g_sw[n], fw1 = g_sw[n + 1];
            float fb0 = __ldg(&bias[n])     / __ldg(&scales[n]);
            float fb1 = __ldg(&bias[n + 1]) / __ldg(&scales[n + 1]);
            int mA = m0 + wid * 16 + g;
            float saA = g_sa[mA];
            float saB = g_sa[mA + 8];
            float2 o0, o1;
            o0.x = accI[nt][0] * saA * fw0 + fb0;
            o0.y = accI[nt][1] * saA * fw1 + fb1;
            o1.x = accI[nt][2] * saB * fw0 + fb0;
            o1.y = accI[nt][3] * saB * fw1 + fb1;
            *reinterpret_cast<float2*>(out + (size_t)mA       * N_ROWS + n) = o0;
            *reinterpret_cast<float2*>(out + (size_t)(mA + 8) * N_ROWS + n) = o1;
        }
    }
}

// ---------------- launch ----------------
extern "C" void kernel_launch(void* const* d_in, const int* in_sizes, int n_in,
                              void* d_out, int out_size)
{
    const float* x      = (const float*)d_in[0];
    const float* weight = (const float*)d_in[1];
    const float* bias   = (const float*)d_in[2];
    const float* scales = (const float*)d_in[3];
    float* out = (float*)d_out;

    cudaFuncSetAttribute(gemm_mixed_kernel,
                         cudaFuncAttributeMaxDynamicSharedMemorySize, SMEM_BYTES);

    quant_fused_kernel<<<M_ROWS + N_ROWS, 256>>>(x, weight, scales);

    dim3 grid(N_ROWS / 128, M_ROWS / 128);   // (32, 64)
    gemm_mixed_kernel<<<grid, 256, SMEM_BYTES>>>(bias, scales, out);
}

// round 14
// speedup vs baseline: 1.1341x; 1.0201x over previous
#include <cuda_runtime.h>
#include <cstdint>

#define DDIM   4096
#define M_ROWS 8192
#define N_ROWS 4096
#define KINT   (DDIM / 4)          // 1024 ints per row

__device__ __align__(256) int8_t g_qx[(size_t)M_ROWS * DDIM];
__device__ __align__(256) int8_t g_qw[(size_t)N_ROWS * DDIM];
__device__ float g_sa[M_ROWS];
__device__ float g_sw[N_ROWS];

__device__ __forceinline__ uint32_t smem_u32(const void* p) {
    uint32_t a;
    asm("{ .reg .u64 t; cvta.to.shared.u64 t, %1; cvt.u32.u64 %0, t; }" : "=r"(a) : "l"(p));
    return a;
}
__device__ __forceinline__ void cp4(uint32_t dst, const void* src) {
    asm volatile("cp.async.ca.shared.global [%0], [%1], 4;" :: "r"(dst), "l"(src) : "memory");
}
#define CP_COMMIT()  asm volatile("cp.async.commit_group;" ::: "memory")
#define CP_WAIT(n)   asm volatile("cp.async.wait_group %0;" :: "n"(n) : "memory")

__device__ __forceinline__ void imma16832(int* c, const uint32_t* a, const uint32_t* b) {
    asm volatile(
        "mma.sync.aligned.m16n8k32.row.col.s32.s8.s8.s32 "
        "{%0,%1,%2,%3}, {%4,%5,%6,%7}, {%8,%9}, {%0,%1,%2,%3};\n"
        : "+r"(c[0]), "+r"(c[1]), "+r"(c[2]), "+r"(c[3])
        : "r"(a[0]), "r"(a[1]), "r"(a[2]), "r"(a[3]), "r"(b[0]), "r"(b[1]));
}

// ---------------- fused row-wise absmax int8 quantization ----------------
__global__ __launch_bounds__(256) void quant_fused_kernel(
    const float* __restrict__ x, const float* __restrict__ w,
    const float* __restrict__ scales)
{
    const int b    = blockIdx.x;
    const bool isx = (b < M_ROWS);
    const int row  = isx ? b : (b - M_ROWS);
    const int tid  = threadIdx.x;
    const float4* src4 = reinterpret_cast<const float4*>((isx ? x : w) + (size_t)row * DDIM);
    const float4* scl4 = reinterpret_cast<const float4*>(scales);

    float v[16];
    float m = 0.f;
    #pragma unroll
    for (int i = 0; i < 4; i++) {
        int g = i * 256 + tid;
        float4 xv = src4[g];
        float4 s  = scl4[g];
        float t0, t1, t2, t3;
        if (isx) { t0 = xv.x * s.x; t1 = xv.y * s.y; t2 = xv.z * s.z; t3 = xv.w * s.w; }
        else     { t0 = xv.x / s.x; t1 = xv.y / s.y; t2 = xv.z / s.z; t3 = xv.w / s.w; }
        v[i*4+0] = t0; v[i*4+1] = t1; v[i*4+2] = t2; v[i*4+3] = t3;
        m = fmaxf(m, fmaxf(fmaxf(fabsf(t0), fabsf(t1)), fmaxf(fabsf(t2), fabsf(t3))));
    }

    __shared__ float red[8];
    #pragma unroll
    for (int o = 16; o > 0; o >>= 1)
        m = fmaxf(m, __shfl_xor_sync(0xffffffffu, m, o));
    if ((tid & 31) == 0) red[tid >> 5] = m;
    __syncthreads();
    if (tid < 32) {
        float t = (tid < 8) ? red[tid] : 0.f;
        #pragma unroll
        for (int o = 4; o > 0; o >>= 1)
            t = fmaxf(t, __shfl_xor_sync(0xffffffffu, t, o));
        if (tid == 0) red[0] = fmaxf(t, 1e-8f);
    }
    __syncthreads();
    const float absmax = red[0];
    const float qs = 127.f / absmax;

    int* qrow = reinterpret_cast<int*>((isx ? g_qx : g_qw) + (size_t)row * DDIM);
    #pragma unroll
    for (int i = 0; i < 4; i++) {
        int g = i * 256 + tid;
        int packed = 0;
        #pragma unroll
        for (int j = 0; j < 4; j++) {
            float t = rintf(v[i*4+j] * qs);
            t = fminf(fmaxf(t, -127.f), 127.f);
            packed |= ((int)t & 0xff) << (8 * j);
        }
        qrow[g] = packed;
    }
    if (tid == 0) {
        if (isx) g_sa[row] = absmax * (1.f / 127.f);
        else     g_sw[row] = absmax * (1.f / 127.f);
    }
}

// ---------------- hybrid GEMM, arbiter-aware warp roles ----------------
// CTA 128x128, K-chunk 16 ints, 3-stage ring, one __syncthreads per chunk.
//   wid 0-3 (LOW priority):  IMMA on n[64:128) + ALL cp.async loading
//   wid 4-7 (HIGH priority): pure dp4a stream on n[0:64)
// hi-wid-first SMSP arbiter then guarantees dp4a its rt=2 issue cadence;
// IMMA + loader fill leftover slots (tensor needs only ~10% issue duty).
#define NCHUNK (KINT / 16)       // 64
#define TSTR   136               // ints per smem row (128 + 8 pad)
#define STAGE_I (16 * TSTR)
#define SMEM_BYTES (3 * 2 * STAGE_I * 4)   // 52224

__global__ __launch_bounds__(256, 2) void gemm_hybrid_kernel(
    const float* __restrict__ bias, const float* __restrict__ scales,
    float* __restrict__ out)
{
    extern __shared__ int smem[];
    int* As = smem;                    // [3][16][TSTR]
    int* Bs = smem + 3 * STAGE_I;      // [3][16][TSTR]

    const int tid  = threadIdx.x;
    const int wid  = tid >> 5;
    const int lane = tid & 31;
    const int m0   = blockIdx.y * 128;
    const int n0   = blockIdx.x * 128;

    const int* qxi = reinterpret_cast<const int*>(g_qx);
    const int* qwi = reinterpret_cast<const int*>(g_qw);
    const uint32_t aBase = smem_u32(As);
    const uint32_t bBase = smem_u32(Bs);

    if (wid < 4) {
        // ============ IMMA + loader warps (threads 0-127, LOW priority) ============
        const int t = tid;            // 0..127

        // loader: 128 threads cover 2048 (m,ki) cells; 2 cp4 (A+B) per cell
        auto load_stage = [&](int c) {
            const int s = c % 3;
            #pragma unroll
            for (int j = 0; j < 16; j++) {
                int idx = j * 128 + t;            // 0..2047
                int m = idx >> 4, ki = idx & 15;
                uint32_t d = (uint32_t)((s * 16 + ki) * TSTR + m) * 4;
                cp4(aBase + d, qxi + (size_t)(m0 + m) * KINT + c * 16 + ki);
                cp4(bBase + d, qwi + (size_t)(n0 + m) * KINT + c * 16 + ki);
            }
        };

        const int wm  = wid >> 1;       // m-offset wm*64
        const int wn  = wid & 1;        // n-offset 64 + wn*32
        const int g   = lane >> 2;
        const int tig = lane & 3;
        int acc[4][4][4];
        #pragma unroll
        for (int i = 0; i < 4; i++)
            #pragma unroll
            for (int j = 0; j < 4; j++)
                #pragma unroll
                for (int k = 0; k < 4; k++) acc[i][j][k] = 0;

        load_stage(0); CP_COMMIT();
        load_stage(1); CP_COMMIT();
        for (int c = 0; c < NCHUNK; c++) {
            CP_WAIT(1);
            __syncthreads();
            if (c + 2 < NCHUNK) { load_stage(c + 2); CP_COMMIT(); }
            const int sO = (c % 3) * 16;
            #pragma unroll
            for (int ks = 0; ks < 2; ks++) {
                const int* klor = As + (sO + ks * 8 + tig) * TSTR;
                const int* khir = As + (sO + ks * 8 + tig + 4) * TSTR;
                const int* klob = Bs + (sO + ks * 8 + tig) * TSTR;
                const int* khib = Bs + (sO + ks * 8 + tig + 4) * TSTR;
                uint32_t a[4][4], b[4][2];
                #pragma unroll
                for (int mt = 0; mt < 4; mt++) {
                    int r = wm * 64 + mt * 16 + g;
                    a[mt][0] = (uint32_t)klor[r];
                    a[mt][1] = (uint32_t)klor[r + 8];
                    a[mt][2] = (uint32_t)khir[r];
                    a[mt][3] = (uint32_t)khir[r + 8];
                }
                #pragma unroll
                for (int nt = 0; nt < 4; nt++) {
                    int n = 64 + wn * 32 + nt * 8 + g;
                    b[nt][0] = (uint32_t)klob[n];
                    b[nt][1] = (uint32_t)khib[n];
                }
                #pragma unroll
                for (int mt = 0; mt < 4; mt++)
                    #pragma unroll
                    for (int nt = 0; nt < 4; nt++)
                        imma16832(acc[mt][nt], a[mt], b[nt]);
            }
        }

        // IMMA epilogue (C frag: c0 (g,2tig), c1 (g,2tig+1), c2 (g+8,2tig), c3 (g+8,2tig+1))
        float fw[4][2], fb[4][2];
        #pragma unroll
        for (int nt = 0; nt < 4; nt++) {
            int n = n0 + 64 + wn * 32 + nt * 8 + 2 * tig;
            fw[nt][0] = g_sw[n];
            fw[nt][1] = g_sw[n + 1];
            fb[nt][0] = __ldg(&bias[n])     / __ldg(&scales[n]);
            fb[nt][1] = __ldg(&bias[n + 1]) / __ldg(&scales[n + 1]);
        }
        #pragma unroll
        for (int mt = 0; mt < 4; mt++) {
            int mA = m0 + wm * 64 + mt * 16 + g;
            float saA = g_sa[mA];
            float saB = g_sa[mA + 8];
            #pragma unroll
            for (int nt = 0; nt < 4; nt++) {
                int n = n0 + 64 + wn * 32 + nt * 8 + 2 * tig;
                float2 o0, o1;
                o0.x = acc[mt][nt][0] * saA * fw[nt][0] + fb[nt][0];
                o0.y = acc[mt][nt][1] * saA * fw[nt][1] + fb[nt][1];
                o1.x = acc[mt][nt][2] * saB * fw[nt][0] + fb[nt][0];
                o1.y = acc[mt][nt][3] * saB * fw[nt][1] + fb[nt][1];
                *reinterpret_cast<float2*>(out + (size_t)mA       * N_ROWS + n) = o0;
                *reinterpret_cast<float2*>(out + (size_t)(mA + 8) * N_ROWS + n) = o1;
            }
        }
    } else {
        // ============ dp4a warps (threads 128-255, HIGH priority, no loads) ============
        const int t  = tid - 128;     // 0..127
        const int ty = t >> 3;        // 0..15 (m)
        const int tx = t & 7;         // 0..7  (n)
        int acc[8][8];
        #pragma unroll
        for (int i = 0; i < 8; i++)
            #pragma unroll
            for (int j = 0; j < 8; j++) acc[i][j] = 0;

        for (int c = 0; c < NCHUNK; c++) {
            __syncthreads();          // stage c ready (loader warps waited before barrier)
            const int sO = (c % 3) * 16;
            #pragma unroll
            for (int ki = 0; ki < 16; ki++) {
                const int* arow = As + (sO + ki) * TSTR;
                const int* brow = Bs + (sO + ki) * TSTR;
                int a[8], b[8];
                *reinterpret_cast<int4*>(&a[0]) = *reinterpret_cast<const int4*>(arow + ty * 8);
                *reinterpret_cast<int4*>(&a[4]) = *reinterpret_cast<const int4*>(arow + ty * 8 + 4);
                *reinterpret_cast<int4*>(&b[0]) = *reinterpret_cast<const int4*>(brow + tx * 8);
                *reinterpret_cast<int4*>(&b[4]) = *reinterpret_cast<const int4*>(brow + tx * 8 + 4);
                #pragma unroll
                for (int i = 0; i < 8; i++)
                    #pragma unroll
                    for (int j = 0; j < 8; j++)
                        acc[i][j] = __dp4a(a[i], b[j], acc[i][j]);
            }
        }

        // dp4a epilogue: m = m0+ty*8+i, n = n0+tx*8+j
        float fw[8], fb[8];
        #pragma unroll
        for (int j = 0; j < 8; j++) {
            int n = n0 + tx * 8 + j;
            fw[j] = g_sw[n];
            fb[j] = __ldg(&bias[n]) / __ldg(&scales[n]);
        }
        #pragma unroll
        for (int i = 0; i < 8; i++) {
            int m = m0 + ty * 8 + i;
            float fa = g_sa[m];
            float4 o0, o1;
            o0.x = acc[i][0]*fa*fw[0]+fb[0]; o0.y = acc[i][1]*fa*fw[1]+fb[1];
            o0.z = acc[i][2]*fa*fw[2]+fb[2]; o0.w = acc[i][3]*fa*fw[3]+fb[3];
            o1.x = acc[i][4]*fa*fw[4]+fb[4]; o1.y = acc[i][5]*fa*fw[5]+fb[5];
            o1.z = acc[i][6]*fa*fw[6]+fb[6]; o1.w = acc[i][7]*fa*fw[7]+fb[7];
            float4* orow = reinterpret_cast<float4*>(out + (size_t)m * N_ROWS + n0 + tx * 8);
            orow[0] = o0; orow[1] = o1;
        }
    }
}

// ---------------- launch ----------------
extern "C" void kernel_launch(void* const* d_in, const int* in_sizes, int n_in,
                              void* d_out, int out_size)
{
    const float* x      = (const float*)d_in[0];
    const float* weight = (const float*)d_in[1];
    const float* bias   = (const float*)d_in[2];
    const float* scales = (const float*)d_in[3];
    float* out = (float*)d_out;

    cudaFuncSetAttribute(gemm_hybrid_kernel,
                         cudaFuncAttributeMaxDynamicSharedMemorySize, SMEM_BYTES);

    quant_fused_kernel<<<M_ROWS + N_ROWS, 256>>>(x, weight, scales);

    dim3 grid(N_ROWS / 128, M_ROWS / 128);   // (32, 64)
    gemm_hybrid_kernel<<<grid, 256, SMEM_BYTES>>>(bias, scales, out);
}

// round 16
// speedup vs baseline: 1.1532x; 1.0168x over previous
#include <cuda_runtime.h>
#include <cstdint>

#define DDIM   4096
#define M_ROWS 8192
#define N_ROWS 4096
#define KINT   (DDIM / 4)          // 1024 ints per row

__device__ __align__(256) int8_t g_qx[(size_t)M_ROWS * DDIM];
__device__ __align__(256) int8_t g_qw[(size_t)N_ROWS * DDIM];
__device__ float g_sa[M_ROWS];
__device__ float g_sw[N_ROWS];

__device__ __forceinline__ uint32_t smem_u32(const void* p) {
    uint32_t a;
    asm("{ .reg .u64 t; cvta.to.shared.u64 t, %1; cvt.u32.u64 %0, t; }" : "=r"(a) : "l"(p));
    return a;
}
__device__ __forceinline__ void cp4(uint32_t dst, const void* src) {
    asm volatile("cp.async.ca.shared.global [%0], [%1], 4;" :: "r"(dst), "l"(src) : "memory");
}
#define CP_COMMIT()  asm volatile("cp.async.commit_group;" ::: "memory")
#define CP_WAIT(n)   asm volatile("cp.async.wait_group %0;" :: "n"(n) : "memory")

__device__ __forceinline__ void imma16832(int* c, const uint32_t* a, const uint32_t* b) {
    asm volatile(
        "mma.sync.aligned.m16n8k32.row.col.s32.s8.s8.s32 "
        "{%0,%1,%2,%3}, {%4,%5,%6,%7}, {%8,%9}, {%0,%1,%2,%3};\n"
        : "+r"(c[0]), "+r"(c[1]), "+r"(c[2]), "+r"(c[3])
        : "r"(a[0]), "r"(a[1]), "r"(a[2]), "r"(a[3]), "r"(b[0]), "r"(b[1]));
}

// ---------------- fused row-wise absmax int8 quantization ----------------
__global__ __launch_bounds__(256) void quant_fused_kernel(
    const float* __restrict__ x, const float* __restrict__ w,
    const float* __restrict__ scales)
{
    const int b    = blockIdx.x;
    const bool isx = (b < M_ROWS);
    const int row  = isx ? b : (b - M_ROWS);
    const int tid  = threadIdx.x;
    const float4* src4 = reinterpret_cast<const float4*>((isx ? x : w) + (size_t)row * DDIM);
    const float4* scl4 = reinterpret_cast<const float4*>(scales);

    float v[16];
    float m = 0.f;
    #pragma unroll
    for (int i = 0; i < 4; i++) {
        int g = i * 256 + tid;
        float4 xv = src4[g];
        float4 s  = scl4[g];
        float t0, t1, t2, t3;
        if (isx) { t0 = xv.x * s.x; t1 = xv.y * s.y; t2 = xv.z * s.z; t3 = xv.w * s.w; }
        else     { t0 = xv.x / s.x; t1 = xv.y / s.y; t2 = xv.z / s.z; t3 = xv.w / s.w; }
        v[i*4+0] = t0; v[i*4+1] = t1; v[i*4+2] = t2; v[i*4+3] = t3;
        m = fmaxf(m, fmaxf(fmaxf(fabsf(t0), fabsf(t1)), fmaxf(fabsf(t2), fabsf(t3))));
    }

    __shared__ float red[8];
    #pragma unroll
    for (int o = 16; o > 0; o >>= 1)
        m = fmaxf(m, __shfl_xor_sync(0xffffffffu, m, o));
    if ((tid & 31) == 0) red[tid >> 5] = m;
    __syncthreads();
    if (tid < 32) {
        float t = (tid < 8) ? red[tid] : 0.f;
        #pragma unroll
        for (int o = 4; o > 0; o >>= 1)
            t = fmaxf(t, __shfl_xor_sync(0xffffffffu, t, o));
        if (tid == 0) red[0] = fmaxf(t, 1e-8f);
    }
    __syncthreads();
    const float absmax = red[0];
    const float qs = 127.f / absmax;

    int* qrow = reinterpret_cast<int*>((isx ? g_qx : g_qw) + (size_t)row * DDIM);
    #pragma unroll
    for (int i = 0; i < 4; i++) {
        int g = i * 256 + tid;
        int packed = 0;
        #pragma unroll
        for (int j = 0; j < 4; j++) {
            float t = rintf(v[i*4+j] * qs);
            t = fminf(fmaxf(t, -127.f), 127.f);
            packed |= ((int)t & 0xff) << (8 * j);
        }
        qrow[g] = packed;
    }
    if (tid == 0) {
        if (isx) g_sa[row] = absmax * (1.f / 127.f);
        else     g_sw[row] = absmax * (1.f / 127.f);
    }
}

// ---------------- hybrid GEMM: arbiter roles + XOR bank swizzle ----------------
// CTA 128x128, K-chunk 16 ints, 3-stage ring, one __syncthreads per chunk.
//   wid 0-3 (LOW priority):  IMMA on n[64:128) + ALL cp.async loading
//   wid 4-7 (HIGH priority): pure dp4a stream on n[0:64)
// Smem tiles [ki][col] (col = m or n), stride TSTR=136 ints. Column stored at
// 16B-group  phys(g, ki) = (g ^ ((g>>3)&1)) ^ (ki&7)   (bijective per row).
// This makes loader writes 2-way (was 4-way), dp4a B reads conflict-free
// (was 2-way), and keeps dp4a A (broadcast) + IMMA scalar reads conflict-free.
#define NCHUNK (KINT / 16)       // 64
#define TSTR   136               // ints per smem row
#define STAGE_I (16 * TSTR)
#define SMEM_BYTES (3 * 2 * STAGE_I * 4)   // 52224

__global__ __launch_bounds__(256, 2) void gemm_hybrid_kernel(
    const float* __restrict__ bias, const float* __restrict__ scales,
    float* __restrict__ out)
{
    extern __shared__ int smem[];
    int* As = smem;                    // [3][16][TSTR]
    int* Bs = smem + 3 * STAGE_I;      // [3][16][TSTR]

    const int tid  = threadIdx.x;
    const int wid  = tid >> 5;
    const int lane = tid & 31;
    const int m0   = blockIdx.y * 128;
    const int n0   = blockIdx.x * 128;

    const int* qxi = reinterpret_cast<const int*>(g_qx);
    const int* qwi = reinterpret_cast<const int*>(g_qw);
    const uint32_t aBase = smem_u32(As);
    const uint32_t bBase = smem_u32(Bs);

    if (wid < 4) {
        // ============ IMMA + loader warps (threads 0-127, LOW priority) ============
        const int t = tid;            // 0..127

        auto load_stage = [&](int c) {
            const int s = c % 3;
            #pragma unroll
            for (int j = 0; j < 16; j++) {
                int idx = j * 128 + t;            // 0..2047
                int m = idx >> 4, ki = idx & 15;
                int gm = m >> 2;
                int col = (((gm ^ ((gm >> 3) & 1)) ^ (ki & 7)) << 2) + (m & 3);
                uint32_t d = (uint32_t)((s * 16 + ki) * TSTR + col) * 4;
                cp4(aBase + d, qxi + (size_t)(m0 + m) * KINT + c * 16 + ki);
                cp4(bBase + d, qwi + (size_t)(n0 + m) * KINT + c * 16 + ki);
            }
        };

        const int wm  = wid >> 1;       // m-offset wm*64
        const int wn  = wid & 1;        // n-offset 64 + wn*32
        const int g   = lane >> 2;
        const int tig = lane & 3;
        const int klo = tig;            // (row ki) & 7 for k-lo rows
        const int khi = tig + 4;        // for k-hi rows
        const int gq  = g >> 2;         // group half select
        const int go  = g & 3;          // offset within 16B group
        int acc[4][4][4];
        #pragma unroll
        for (int i = 0; i < 4; i++)
            #pragma unroll
            for (int j = 0; j < 4; j++)
                #pragma unroll
                for (int k = 0; k < 4; k++) acc[i][j][k] = 0;

        load_stage(0); CP_COMMIT();
        load_stage(1); CP_COMMIT();
        for (int c = 0; c < NCHUNK; c++) {
            CP_WAIT(1);
            __syncthreads();
            if (c + 2 < NCHUNK) { load_stage(c + 2); CP_COMMIT(); }
            const int sO = (c % 3) * 16;
            #pragma unroll
            for (int ks = 0; ks < 2; ks++) {
                const int* rAlo = As + (sO + ks * 8 + tig) * TSTR;
                const int* rAhi = As + (sO + ks * 8 + tig + 4) * TSTR;
                const int* rBlo = Bs + (sO + ks * 8 + tig) * TSTR;
                const int* rBhi = Bs + (sO + ks * 8 + tig + 4) * TSTR;
                uint32_t a[4][4], b[4][2];
                #pragma unroll
                for (int mt = 0; mt < 4; mt++) {
                    int ga  = wm * 16 + mt * 4 + gq;          // group of col r
                    int ga2 = ga + 2;                         // group of col r+8
                    int gaf  = ga  ^ ((ga  >> 3) & 1);
                    int ga2f = ga2 ^ ((ga2 >> 3) & 1);
                    a[mt][0] = (uint32_t)rAlo[((gaf  ^ klo) << 2) + go];
                    a[mt][1] = (uint32_t)rAlo[((ga2f ^ klo) << 2) + go];
                    a[mt][2] = (uint32_t)rAhi[((gaf  ^ khi) << 2) + go];
                    a[mt][3] = (uint32_t)rAhi[((ga2f ^ khi) << 2) + go];
                }
                #pragma unroll
                for (int nt = 0; nt < 4; nt++) {
                    int gb  = 16 + wn * 8 + nt * 2 + gq;      // group of col n
                    int gbf = gb ^ ((gb >> 3) & 1);
                    b[nt][0] = (uint32_t)rBlo[((gbf ^ klo) << 2) + go];
                    b[nt][1] = (uint32_t)rBhi[((gbf ^ khi) << 2) + go];
                }
                #pragma unroll
                for (int mt = 0; mt < 4; mt++)
                    #pragma unroll
                    for (int nt = 0; nt < 4; nt++)
                        imma16832(acc[mt][nt], a[mt], b[nt]);
            }
        }

        // IMMA epilogue (C frag: c0 (g,2tig), c1 (g,2tig+1), c2 (g+8,2tig), c3 (g+8,2tig+1))
        float fw[4][2], fb[4][2];
        #pragma unroll
        for (int nt = 0; nt < 4; nt++) {
            int n = n0 + 64 + wn * 32 + nt * 8 + 2 * tig;
            fw[nt][0] = g_sw[n];
            fw[nt][1] = g_sw[n + 1];
            fb[nt][0] = __ldg(&bias[n])     / __ldg(&scales[n]);
            fb[nt][1] = __ldg(&bias[n + 1]) / __ldg(&scales[n + 1]);
        }
        #pragma unroll
        for (int mt = 0; mt < 4; mt++) {
            int mA = m0 + wm * 64 + mt * 16 + g;
            float saA = g_sa[mA];
            float saB = g_sa[mA + 8];
            #pragma unroll
            for (int nt = 0; nt < 4; nt++) {
                int n = n0 + 64 + wn * 32 + nt * 8 + 2 * tig;
                float2 o0, o1;
                o0.x = acc[mt][nt][0] * saA * fw[nt][0] + fb[nt][0];
                o0.y = acc[mt][nt][1] * saA * fw[nt][1] + fb[nt][1];
                o1.x = acc[mt][nt][2] * saB * fw[nt][0] + fb[nt][0];
                o1.y = acc[mt][nt][3] * saB * fw[nt][1] + fb[nt][1];
                *reinterpret_cast<float2*>(out + (size_t)mA       * N_ROWS + n) = o0;
                *reinterpret_cast<float2*>(out + (size_t)(mA + 8) * N_ROWS + n) = o1;
            }
        }
    } else {
        // ============ dp4a warps (threads 128-255, HIGH priority, no loads) ============
        const int t  = tid - 128;     // 0..127
        const int ty = t >> 3;        // 0..15 (m)
        const int tx = t & 7;         // 0..7  (n)
        // precomputed swizzle keys: PH(g, ki) = (g ^ ((g>>3)&1)) ^ (ki&7)
        const int tyg = 2 * ty;
        const int txg = 2 * tx;
        const int kA0 = tyg       ^ ((tyg >> 3) & 1);
        const int kA1 = (tyg + 1) ^ ((tyg >> 3) & 1);
        const int kB0 = txg       ^ ((txg >> 3) & 1);
        const int kB1 = (txg + 1) ^ ((txg >> 3) & 1);
        const int4* As4 = reinterpret_cast<const int4*>(As);
        const int4* Bs4 = reinterpret_cast<const int4*>(Bs);
        int acc[8][8];
        #pragma unroll
        for (int i = 0; i < 8; i++)
            #pragma unroll
            for (int j = 0; j < 8; j++) acc[i][j] = 0;

        for (int c = 0; c < NCHUNK; c++) {
            __syncthreads();          // stage c ready (loader warps waited before barrier)
            const int sO = (c % 3) * 16;
            #pragma unroll
            for (int ki = 0; ki < 16; ki++) {
                const int4* arow = As4 + (sO + ki) * (TSTR / 4);
                const int4* brow = Bs4 + (sO + ki) * (TSTR / 4);
                const int k7 = ki & 7;
                int a[8], b[8];
                *reinterpret_cast<int4*>(&a[0]) = arow[kA0 ^ k7];
                *reinterpret_cast<int4*>(&a[4]) = arow[kA1 ^ k7];
                *reinterpret_cast<int4*>(&b[0]) = brow[kB0 ^ k7];
                *reinterpret_cast<int4*>(&b[4]) = brow[kB1 ^ k7];
                #pragma unroll
                for (int i = 0; i < 8; i++)
                    #pragma unroll
                    for (int j = 0; j < 8; j++)
                        acc[i][j] = __dp4a(a[i], b[j], acc[i][j]);
            }
        }

        // dp4a epilogue: m = m0+ty*8+i, n = n0+tx*8+j
        float fw[8], fb[8];
        #pragma unroll
        for (int j = 0; j < 8; j++) {
            int n = n0 + tx * 8 + j;
            fw[j] = g_sw[n];
            fb[j] = __ldg(&bias[n]) / __ldg(&scales[n]);
        }
        #pragma unroll
        for (int i = 0; i < 8; i++) {
            int m = m0 + ty * 8 + i;
            float fa = g_sa[m];
            float4 o0, o1;
            o0.x = acc[i][0]*fa*fw[0]+fb[0]; o0.y = acc[i][1]*fa*fw[1]+fb[1];
            o0.z = acc[i][2]*fa*fw[2]+fb[2]; o0.w = acc[i][3]*fa*fw[3]+fb[3];
            o1.x = acc[i][4]*fa*fw[4]+fb[4]; o1.y = acc[i][5]*fa*fw[5]+fb[5];
            o1.z = acc[i][6]*fa*fw[6]+fb[6]; o1.w = acc[i][7]*fa*fw[7]+fb[7];
            float4* orow = reinterpret_cast<float4*>(out + (size_t)m * N_ROWS + n0 + tx * 8);
            orow[0] = o0; orow[1] = o1;
        }
    }
}

// ---------------- launch ----------------
extern "C" void kernel_launch(void* const* d_in, const int* in_sizes, int n_in,
                              void* d_out, int out_size)
{
    const float* x      = (const float*)d_in[0];
    const float* weight = (const float*)d_in[1];
    const float* bias   = (const float*)d_in[2];
    const float* scales = (const float*)d_in[3];
    float* out = (float*)d_out;

    cudaFuncSetAttribute(gemm_hybrid_kernel,
                         cudaFuncAttributeMaxDynamicSharedMemorySize, SMEM_BYTES);

    quant_fused_kernel<<<M_ROWS + N_ROWS, 256>>>(x, weight, scales);

    dim3 grid(N_ROWS / 128, M_ROWS / 128);   // (32, 64)
    gemm_hybrid_kernel<<<grid, 256, SMEM_BYTES>>>(bias, scales, out);
}